// round 14
// baseline (speedup 1.0000x reference)
#include <cuda_runtime.h>
#include <cstdint>

#define BATCH   4
#define KCLS    64
#define NSHOT   32
#define DIM     128
#define MTEST   4096
#define TRN     (KCLS * NSHOT)      // 2048
#define TM      128                 // tests per CTA
#define TNC     64                  // trains per chunk (2 classes)
#define NCHUNK  (TRN / TNC)         // 32
#define THREADS 256
#define EPS_RESCUE 1e-3f

// smem float offsets: fragment-order tiles [ks(16)][frag(8)][lane(32)][regs]
#define OFF_AHI  0                  // 16*8*32*4 = 16384 floats
#define OFF_ALO  16384
#define OFF_BHI  32768              // 16*8*32*2 = 8192 floats
#define OFF_BLO  40960
#define OFF_INVN 49152              // 64
#define OFF_TMP  49216              // 128
#define SMEM_FLOATS 49344           // 197376 B

__device__ int g_flag[BATCH * MTEST];

// cvt.rna.tf32.f32 needs a .b32 destination (this was the R13 build break);
// result is fp32-layout bits with low 13 mantissa bits zeroed.
__device__ __forceinline__ float tf32r(float x) {
    uint32_t r;
    asm("cvt.rna.tf32.f32 %0, %1;" : "=r"(r) : "f"(x));
    return __uint_as_float(r);
}
__device__ __forceinline__ void mma_tf32(float* d, const float* a, const float* b) {
    asm volatile(
        "mma.sync.aligned.m16n8k8.row.col.f32.tf32.tf32.f32 "
        "{%0,%1,%2,%3}, {%4,%5,%6,%7}, {%8,%9}, {%0,%1,%2,%3};"
        : "+f"(d[0]), "+f"(d[1]), "+f"(d[2]), "+f"(d[3])
        : "r"(__float_as_uint(a[0])), "r"(__float_as_uint(a[1])),
          "r"(__float_as_uint(a[2])), "r"(__float_as_uint(a[3])),
          "r"(__float_as_uint(b[0])), "r"(__float_as_uint(b[1])));
}

extern __shared__ __align__(16) float sm[];

// ---------------------------------------------------------------------------
// Main kernel: 3xTF32 mma.sync GEMM + fused max/argmax + rescue flag.
//   score(m,n) = dot(test, train_n) * invnorm(train_n)   (test norm dropped)
// Fragments (m16n8k8, row.col):
//   A a0..a3 = (r,c),(r+8,c),(r,c+4),(r+8,c+4), r=lane>>2, c=lane&3
//   B b0,b1  = (k=lane&3, n=lane>>2), (k+4, n)
//   D c0..c3 = (r, 2(lane&3)+{0,1}), (r+8, ...)
// ---------------------------------------------------------------------------
__global__ __launch_bounds__(THREADS, 1)
void ms_mma_kernel(const float* __restrict__ train,
                   const float* __restrict__ test,
                   float* __restrict__ out) {
    const int tid  = threadIdx.x;
    const int lane = tid & 31;
    const int w    = tid >> 5;           // 0..7
    const int b      = blockIdx.y;
    const int m_base = blockIdx.x * TM;

    const float* teg = test  + ((size_t)b * MTEST + m_base) * DIM;
    const float* trg = train + (size_t)b * TRN * DIM;

    const int r4 = lane >> 2;            // 0..7
    const int c4 = lane & 3;             // 0..3

    // ---- A fragments (tests), built once: warp w = mfrag w ---------------
    #pragma unroll 4
    for (int t = 0; t < 16; ++t) {
        int m = w * 16 + r4;
        int c = t * 8 + c4;
        float a0 = teg[m * DIM + c];
        float a1 = teg[(m + 8) * DIM + c];
        float a2 = teg[m * DIM + c + 4];
        float a3 = teg[(m + 8) * DIM + c + 4];
        float4 h, l;
        h.x = tf32r(a0); h.y = tf32r(a1); h.z = tf32r(a2); h.w = tf32r(a3);
        l.x = tf32r(a0 - h.x); l.y = tf32r(a1 - h.y);
        l.z = tf32r(a2 - h.z); l.w = tf32r(a3 - h.w);
        int base = ((t * 8 + w) * 32 + lane) * 4;
        *(float4*)&sm[OFF_AHI + base] = h;
        *(float4*)&sm[OFF_ALO + base] = l;
    }

    const int nw = w & 1;                // n-warp: class parity within chunk
    const int mb = (w >> 1) * 2;         // first mfrag of this warp

    float bestv[4], best2v[4];
    int   bestk[4];
    #pragma unroll
    for (int i = 0; i < 4; ++i) {
        bestv[i] = -3.402823466e38f; best2v[i] = -3.402823466e38f; bestk[i] = 0;
    }

    for (int chunk = 0; chunk < NCHUNK; ++chunk) {
        __syncthreads();   // prev compute done reading B frags / tmp / invn

        // ---- train-row inverse norms (warp w -> rows 8w..8w+7) ----------
        #pragma unroll
        for (int it = 0; it < 8; ++it) {
            int n = w * 8 + it;
            float4 v = *(const float4*)(trg + (size_t)(chunk * TNC + n) * DIM + lane * 4);
            float s = v.x * v.x + v.y * v.y + v.z * v.z + v.w * v.w;
            #pragma unroll
            for (int o = 16; o; o >>= 1) s += __shfl_xor_sync(0xffffffffu, s, o);
            if (lane == 0) sm[OFF_INVN + n] = 1.0f / fmaxf(sqrtf(s), 1e-8f);
        }

        // ---- B fragments (warp w = nfrag w) ------------------------------
        #pragma unroll 4
        for (int t = 0; t < 16; ++t) {
            int n = chunk * TNC + w * 8 + r4;
            int k = t * 8 + c4;
            float b0 = trg[(size_t)n * DIM + k];
            float b1 = trg[(size_t)n * DIM + k + 4];
            float h0 = tf32r(b0), h1 = tf32r(b1);
            float l0 = tf32r(b0 - h0), l1 = tf32r(b1 - h1);
            int base = ((t * 8 + w) * 32 + lane) * 2;
            *(float2*)&sm[OFF_BHI + base] = make_float2(h0, h1);
            *(float2*)&sm[OFF_BLO + base] = make_float2(l0, l1);
        }
        __syncthreads();

        // ---- compute: warp tile 32m x 32n, 16 kslices x 3 split-MMAs -----
        float d[2][4][4];
        #pragma unroll
        for (int i = 0; i < 2; ++i)
            #pragma unroll
            for (int j = 0; j < 4; ++j)
                #pragma unroll
                for (int q = 0; q < 4; ++q) d[i][j][q] = 0.0f;

        #pragma unroll 2
        for (int ks = 0; ks < 16; ++ks) {
            float ah[2][4], al[2][4];
            #pragma unroll
            for (int i = 0; i < 2; ++i) {
                int base = ((ks * 8 + mb + i) * 32 + lane) * 4;
                *(float4*)ah[i] = *(const float4*)&sm[OFF_AHI + base];
                *(float4*)al[i] = *(const float4*)&sm[OFF_ALO + base];
            }
            float bh[4][2], bl[4][2];
            #pragma unroll
            for (int j = 0; j < 4; ++j) {
                int base = ((ks * 8 + nw * 4 + j) * 32 + lane) * 2;
                *(float2*)bh[j] = *(const float2*)&sm[OFF_BHI + base];
                *(float2*)bl[j] = *(const float2*)&sm[OFF_BLO + base];
            }
            #pragma unroll
            for (int i = 0; i < 2; ++i)
                #pragma unroll
                for (int j = 0; j < 4; ++j) {
                    mma_tf32(d[i][j], ah[i], bh[j]);
                    mma_tf32(d[i][j], ah[i], bl[j]);
                    mma_tf32(d[i][j], al[i], bh[j]);
                }
        }

        // ---- epilogue: invnorm fold, max over class shots ----------------
        float winv[4][2];
        #pragma unroll
        for (int j = 0; j < 4; ++j) {
            int ncol = nw * 32 + j * 8 + 2 * c4;
            winv[j][0] = sm[OFF_INVN + ncol];
            winv[j][1] = sm[OFF_INVN + ncol + 1];
        }

        float rowv[4];
        #pragma unroll
        for (int i = 0; i < 2; ++i)
            #pragma unroll
            for (int half = 0; half < 2; ++half) {
                float v = -3.402823466e38f;
                #pragma unroll
                for (int j = 0; j < 4; ++j)
                    v = fmaxf(v, fmaxf(d[i][j][half * 2]     * winv[j][0],
                                       d[i][j][half * 2 + 1] * winv[j][1]));
                v = fmaxf(v, __shfl_xor_sync(0xffffffffu, v, 1));
                v = fmaxf(v, __shfl_xor_sync(0xffffffffu, v, 2));
                rowv[i * 2 + half] = v;   // valid on lanes with (lane&3)==0
            }

        // odd-class warps publish their class scores
        if (nw == 1 && c4 == 0) {
            #pragma unroll
            for (int idx = 0; idx < 4; ++idx) {
                int row = (w >> 1) * 32 + (idx >> 1) * 16 + (idx & 1) * 8 + r4;
                sm[OFF_TMP + row] = rowv[idx];
            }
        }
        __syncthreads();
        // even-class warps do the running argmax (ascending class order)
        if (nw == 0 && c4 == 0) {
            #pragma unroll
            for (int idx = 0; idx < 4; ++idx) {
                int row = (w >> 1) * 32 + (idx >> 1) * 16 + (idx & 1) * 8 + r4;
                float v0 = rowv[idx];            // class 2*chunk
                float v1 = sm[OFF_TMP + row];    // class 2*chunk+1
                if (v0 > bestv[idx]) { best2v[idx] = bestv[idx]; bestv[idx] = v0; bestk[idx] = 2 * chunk; }
                else if (v0 > best2v[idx]) best2v[idx] = v0;
                if (v1 > bestv[idx]) { best2v[idx] = bestv[idx]; bestv[idx] = v1; bestk[idx] = 2 * chunk + 1; }
                else if (v1 > best2v[idx]) best2v[idx] = v1;
            }
        }
    }

    // ---- write tentative labels (float32) + rescue flags ------------------
    if (nw == 0 && c4 == 0) {
        #pragma unroll
        for (int idx = 0; idx < 4; ++idx) {
            int row = (w >> 1) * 32 + (idx >> 1) * 16 + (idx & 1) * 8 + r4;
            int gm  = b * MTEST + m_base + row;
            out[gm]    = (float)bestk[idx];
            g_flag[gm] = (bestv[idx] - best2v[idx] < EPS_RESCUE) ? 1 : 0;
        }
    }
}

// ---------------------------------------------------------------------------
// Rescue kernel: exact fp32 recompute for near-tie tests (reference argmax
// semantics: ascending classes, strict >)
// ---------------------------------------------------------------------------
__global__ __launch_bounds__(128, 8)
void rescue_kernel(const float* __restrict__ train,
                   const float* __restrict__ test,
                   float* __restrict__ out) {
    const int m = blockIdx.x, b = blockIdx.y;
    if (g_flag[b * MTEST + m] == 0) return;

    __shared__ __align__(16) float teS[DIM];
    __shared__ float clsS[KCLS];

    const int tid = threadIdx.x;
    teS[tid] = test[((size_t)b * MTEST + m) * DIM + tid];
    __syncthreads();

    const int w = tid >> 5, l = tid & 31;
    const float* trb = train + (size_t)b * TRN * DIM;

    #pragma unroll 1
    for (int j = 0; j < 16; ++j) {
        int n = tid + 128 * j;                 // class w + 4j, shot l
        const float4* tr4 = (const float4*)(trb + (size_t)n * DIM);
        float dot = 0.0f, ss = 0.0f;
        #pragma unroll
        for (int q = 0; q < 32; ++q) {
            float4 t = tr4[q];
            float4 e = *(const float4*)(teS + q * 4);
            dot += t.x * e.x + t.y * e.y + t.z * e.z + t.w * e.w;
            ss  += t.x * t.x + t.y * t.y + t.z * t.z + t.w * t.w;
        }
        float sc = dot * (1.0f / fmaxf(sqrtf(ss), 1e-8f));
        #pragma unroll
        for (int o = 16; o; o >>= 1) sc = fmaxf(sc, __shfl_xor_sync(0xffffffffu, sc, o));
        if (l == 0) clsS[w + 4 * j] = sc;
    }
    __syncthreads();

    if (tid == 0) {
        float best = -3.402823466e38f;
        int bk = 0;
        #pragma unroll 1
        for (int c = 0; c < KCLS; ++c) {
            float v = clsS[c];
            if (v > best) { best = v; bk = c; }
        }
        out[b * MTEST + m] = (float)bk;
    }
}

// ---------------------------------------------------------------------------
extern "C" void kernel_launch(void* const* d_in, const int* in_sizes, int n_in,
                              void* d_out, int out_size) {
    const float* train;
    const float* test;
    if (in_sizes[0] == BATCH * TRN * DIM) {
        train = (const float*)d_in[0];
        test  = (const float*)d_in[1];
    } else {
        train = (const float*)d_in[1];
        test  = (const float*)d_in[0];
    }
    float* out = (float*)d_out;

    const int smem_bytes = SMEM_FLOATS * (int)sizeof(float);  // ~193 KB
    cudaFuncSetAttribute(ms_mma_kernel,
                         cudaFuncAttributeMaxDynamicSharedMemorySize, smem_bytes);

    dim3 grid(MTEST / TM, BATCH);
    ms_mma_kernel<<<grid, THREADS, smem_bytes>>>(train, test, out);

    dim3 rgrid(MTEST, BATCH);
    rescue_kernel<<<rgrid, 128>>>(train, test, out);
}

// round 15
// speedup vs baseline: 1.5446x; 1.5446x over previous
#include <cuda_runtime.h>
#include <cuda_bf16.h>
#include <cstdint>

#define BATCH   4
#define KCLS    64
#define NSHOT   32
#define DIM     128
#define MTEST   4096
#define TRN     (KCLS * NSHOT)      // 2048
#define TM      128                 // tests per CTA
#define TNC     64                  // trains per chunk (2 classes)
#define NCHUNK  (TRN / TNC)         // 32
#define THREADS 256
#define EPS_RESCUE 1e-3f
#define RGRID   512                 // rescue worker grid

// smem u32 offsets: fragment-order tiles [t(8)][frag(8)][lane(32)][regs]
#define OFF_AHI  0                   // 8*8*32*4 = 8192 u32
#define OFF_ALO  8192
#define OFF_BHI  16384               // 8*8*32*2 = 4096 u32
#define OFF_BLO  20480
#define OFF_INVN 24576               // 64
#define OFF_TMP  24640               // 128
#define SMEM_U32 24768               // 99072 B

__device__ int g_flag[BATCH * MTEST];
__device__ int g_list[BATCH * MTEST];
__device__ int g_count;

// ---------------------------------------------------------------------------
// helpers
// ---------------------------------------------------------------------------
__device__ __forceinline__ uint32_t packbf(float x0, float x1) {
    __nv_bfloat162 h = __floats2bfloat162_rn(x0, x1);   // .x = x0 (low half)
    return *(uint32_t*)&h;
}
__device__ __forceinline__ float bfhi(float x) {
    return __bfloat162float(__float2bfloat16_rn(x));
}
__device__ __forceinline__ void mma_bf16(float* d, const uint32_t* a,
                                         const uint32_t* b) {
    asm volatile(
        "mma.sync.aligned.m16n8k16.row.col.f32.bf16.bf16.f32 "
        "{%0,%1,%2,%3}, {%4,%5,%6,%7}, {%8,%9}, {%0,%1,%2,%3};"
        : "+f"(d[0]), "+f"(d[1]), "+f"(d[2]), "+f"(d[3])
        : "r"(a[0]), "r"(a[1]), "r"(a[2]), "r"(a[3]), "r"(b[0]), "r"(b[1]));
}

extern __shared__ __align__(16) uint32_t sm[];

// ---------------------------------------------------------------------------
// Main kernel: 3x bf16-split mma.sync GEMM + fused max/argmax + rescue flag.
//   score(m,n) = dot(test, train_n) * invnorm(train_n)   (test norm dropped)
// m16n8k16 fragments (row.col), r4 = lane>>2, c4 = lane&3:
//   A a0..a3 = (r4, 2c4..+1), (r4+8, 2c4..+1), (r4, 2c4+8..), (r4+8, 2c4+8..)
//   B b0,b1  = (k=2c4..+1, n=r4), (k=2c4+8.., n=r4)
//   D c0..c3 = (r4, 2c4+{0,1}), (r4+8, ...)   [same as R14 -> epilogue kept]
// ---------------------------------------------------------------------------
__global__ __launch_bounds__(THREADS, 1)
void ms_mma_kernel(const float* __restrict__ train,
                   const float* __restrict__ test,
                   float* __restrict__ out) {
    const int tid  = threadIdx.x;
    const int lane = tid & 31;
    const int w    = tid >> 5;           // 0..7
    const int b      = blockIdx.y;
    const int m_base = blockIdx.x * TM;

    const float* teg = test  + ((size_t)b * MTEST + m_base) * DIM;
    const float* trg = train + (size_t)b * TRN * DIM;

    float* invnS = (float*)&sm[OFF_INVN];
    float* tmpS  = (float*)&sm[OFF_TMP];

    const int r4 = lane >> 2;            // 0..7
    const int c4 = lane & 3;             // 0..3

    // ---- A fragments (tests), built once: warp w = mfrag w ---------------
    #pragma unroll
    for (int t = 0; t < 8; ++t) {        // k16 slice
        int m = w * 16 + r4;
        int k = t * 16 + 2 * c4;
        float2 x0 = *(const float2*)(teg + m * DIM + k);
        float2 x1 = *(const float2*)(teg + (m + 8) * DIM + k);
        float2 x2 = *(const float2*)(teg + m * DIM + k + 8);
        float2 x3 = *(const float2*)(teg + (m + 8) * DIM + k + 8);
        float h[8] = {bfhi(x0.x), bfhi(x0.y), bfhi(x1.x), bfhi(x1.y),
                      bfhi(x2.x), bfhi(x2.y), bfhi(x3.x), bfhi(x3.y)};
        uint4 ah = make_uint4(packbf(h[0], h[1]), packbf(h[2], h[3]),
                              packbf(h[4], h[5]), packbf(h[6], h[7]));
        uint4 al = make_uint4(packbf(x0.x - h[0], x0.y - h[1]),
                              packbf(x1.x - h[2], x1.y - h[3]),
                              packbf(x2.x - h[4], x2.y - h[5]),
                              packbf(x3.x - h[6], x3.y - h[7]));
        int base = ((t * 8 + w) * 32 + lane) * 4;
        *(uint4*)&sm[OFF_AHI + base] = ah;
        *(uint4*)&sm[OFF_ALO + base] = al;
    }

    const int nw = w & 1;                // n-warp: class parity within chunk
    const int mb = (w >> 1) * 2;         // first mfrag of this warp

    float bestv[4], best2v[4];
    int   bestk[4];
    #pragma unroll
    for (int i = 0; i < 4; ++i) {
        bestv[i] = -3.402823466e38f; best2v[i] = -3.402823466e38f; bestk[i] = 0;
    }

    for (int chunk = 0; chunk < NCHUNK; ++chunk) {
        __syncthreads();   // prev compute done reading B frags / tmp / invn

        // ---- train-row inverse norms (warp w -> rows 8w..8w+7) ----------
        #pragma unroll
        for (int it = 0; it < 8; ++it) {
            int n = w * 8 + it;
            float4 v = *(const float4*)(trg + (size_t)(chunk * TNC + n) * DIM + lane * 4);
            float s = v.x * v.x + v.y * v.y + v.z * v.z + v.w * v.w;
            #pragma unroll
            for (int o = 16; o; o >>= 1) s += __shfl_xor_sync(0xffffffffu, s, o);
            if (lane == 0) invnS[n] = 1.0f / fmaxf(sqrtf(s), 1e-8f);
        }

        // ---- B fragments (warp w = nfrag w) ------------------------------
        #pragma unroll
        for (int t = 0; t < 8; ++t) {
            int n = chunk * TNC + w * 8 + r4;
            int k = t * 16 + 2 * c4;
            float2 y0 = *(const float2*)(trg + (size_t)n * DIM + k);
            float2 y1 = *(const float2*)(trg + (size_t)n * DIM + k + 8);
            float h0 = bfhi(y0.x), h1 = bfhi(y0.y);
            float h2 = bfhi(y1.x), h3 = bfhi(y1.y);
            int base = ((t * 8 + w) * 32 + lane) * 2;
            *(uint2*)&sm[OFF_BHI + base] =
                make_uint2(packbf(h0, h1), packbf(h2, h3));
            *(uint2*)&sm[OFF_BLO + base] =
                make_uint2(packbf(y0.x - h0, y0.y - h1),
                           packbf(y1.x - h2, y1.y - h3));
        }
        __syncthreads();

        // ---- compute: warp tile 32m x 32n, 8 k16-slices x 3 split-MMAs ---
        float d[2][4][4];
        #pragma unroll
        for (int i = 0; i < 2; ++i)
            #pragma unroll
            for (int j = 0; j < 4; ++j)
                #pragma unroll
                for (int q = 0; q < 4; ++q) d[i][j][q] = 0.0f;

        #pragma unroll
        for (int t = 0; t < 8; ++t) {
            uint32_t ah[2][4], al[2][4];
            #pragma unroll
            for (int i = 0; i < 2; ++i) {
                int base = ((t * 8 + mb + i) * 32 + lane) * 4;
                *(uint4*)ah[i] = *(const uint4*)&sm[OFF_AHI + base];
                *(uint4*)al[i] = *(const uint4*)&sm[OFF_ALO + base];
            }
            uint32_t bh[4][2], bl[4][2];
            #pragma unroll
            for (int j = 0; j < 4; ++j) {
                int base = ((t * 8 + nw * 4 + j) * 32 + lane) * 2;
                *(uint2*)bh[j] = *(const uint2*)&sm[OFF_BHI + base];
                *(uint2*)bl[j] = *(const uint2*)&sm[OFF_BLO + base];
            }
            // split-major order: 8 independent accumulators between
            // same-d MMAs (no 3-deep RAW chains)
            #pragma unroll
            for (int i = 0; i < 2; ++i)
                #pragma unroll
                for (int j = 0; j < 4; ++j) mma_bf16(d[i][j], ah[i], bh[j]);
            #pragma unroll
            for (int i = 0; i < 2; ++i)
                #pragma unroll
                for (int j = 0; j < 4; ++j) mma_bf16(d[i][j], ah[i], bl[j]);
            #pragma unroll
            for (int i = 0; i < 2; ++i)
                #pragma unroll
                for (int j = 0; j < 4; ++j) mma_bf16(d[i][j], al[i], bh[j]);
        }

        // ---- epilogue: invnorm fold, max over class shots (as R14) -------
        float winv[4][2];
        #pragma unroll
        for (int j = 0; j < 4; ++j) {
            int ncol = nw * 32 + j * 8 + 2 * c4;
            winv[j][0] = invnS[ncol];
            winv[j][1] = invnS[ncol + 1];
        }

        float rowv[4];
        #pragma unroll
        for (int i = 0; i < 2; ++i)
            #pragma unroll
            for (int half = 0; half < 2; ++half) {
                float v = -3.402823466e38f;
                #pragma unroll
                for (int j = 0; j < 4; ++j)
                    v = fmaxf(v, fmaxf(d[i][j][half * 2]     * winv[j][0],
                                       d[i][j][half * 2 + 1] * winv[j][1]));
                v = fmaxf(v, __shfl_xor_sync(0xffffffffu, v, 1));
                v = fmaxf(v, __shfl_xor_sync(0xffffffffu, v, 2));
                rowv[i * 2 + half] = v;   // valid on lanes with (lane&3)==0
            }

        if (nw == 1 && c4 == 0) {
            #pragma unroll
            for (int idx = 0; idx < 4; ++idx) {
                int row = (w >> 1) * 32 + (idx >> 1) * 16 + (idx & 1) * 8 + r4;
                tmpS[row] = rowv[idx];
            }
        }
        __syncthreads();
        if (nw == 0 && c4 == 0) {
            #pragma unroll
            for (int idx = 0; idx < 4; ++idx) {
                int row = (w >> 1) * 32 + (idx >> 1) * 16 + (idx & 1) * 8 + r4;
                float v0 = rowv[idx];            // class 2*chunk
                float v1 = tmpS[row];            // class 2*chunk+1
                if (v0 > bestv[idx]) { best2v[idx] = bestv[idx]; bestv[idx] = v0; bestk[idx] = 2 * chunk; }
                else if (v0 > best2v[idx]) best2v[idx] = v0;
                if (v1 > bestv[idx]) { best2v[idx] = bestv[idx]; bestv[idx] = v1; bestk[idx] = 2 * chunk + 1; }
                else if (v1 > best2v[idx]) best2v[idx] = v1;
            }
        }
    }

    if (nw == 0 && c4 == 0) {
        #pragma unroll
        for (int idx = 0; idx < 4; ++idx) {
            int row = (w >> 1) * 32 + (idx >> 1) * 16 + (idx & 1) * 8 + r4;
            int gm  = b * MTEST + m_base + row;
            out[gm]    = (float)bestk[idx];
            g_flag[gm] = (bestv[idx] - best2v[idx] < EPS_RESCUE) ? 1 : 0;
        }
    }
}

// ---------------------------------------------------------------------------
// Rescue path: zero counter -> compact flagged indices -> fixed worker grid
// ---------------------------------------------------------------------------
__global__ void zero_kernel() { g_count = 0; }

__global__ __launch_bounds__(1024)
void compact_kernel() {
    int idx = blockIdx.x * 1024 + threadIdx.x;
    if (idx < BATCH * MTEST && g_flag[idx]) {
        int pos = atomicAdd(&g_count, 1);
        g_list[pos] = idx;
    }
}

__global__ __launch_bounds__(128, 8)
void rescue_kernel(const float* __restrict__ train,
                   const float* __restrict__ test,
                   float* __restrict__ out) {
    __shared__ __align__(16) float teS[DIM];
    __shared__ float clsS[KCLS];

    const int tid = threadIdx.x;
    const int w = tid >> 5, l = tid & 31;
    const int cnt = g_count;

    for (int q = blockIdx.x; q < cnt; q += RGRID) {
        int idx = g_list[q];
        int b = idx / MTEST, m = idx % MTEST;

        __syncthreads();
        teS[tid] = test[((size_t)b * MTEST + m) * DIM + tid];
        __syncthreads();

        const float* trb = train + (size_t)b * TRN * DIM;
        #pragma unroll 1
        for (int j = 0; j < 16; ++j) {
            int n = tid + 128 * j;                 // class w + 4j, shot l
            const float4* tr4 = (const float4*)(trb + (size_t)n * DIM);
            float dot = 0.0f, ss = 0.0f;
            #pragma unroll
            for (int qq = 0; qq < 32; ++qq) {
                float4 t = tr4[qq];
                float4 e = *(const float4*)(teS + qq * 4);
                dot += t.x * e.x + t.y * e.y + t.z * e.z + t.w * e.w;
                ss  += t.x * t.x + t.y * t.y + t.z * t.z + t.w * t.w;
            }
            float sc = dot * (1.0f / fmaxf(sqrtf(ss), 1e-8f));
            #pragma unroll
            for (int o = 16; o; o >>= 1)
                sc = fmaxf(sc, __shfl_xor_sync(0xffffffffu, sc, o));
            if (l == 0) clsS[w + 4 * j] = sc;
        }
        __syncthreads();

        if (tid == 0) {
            float best = -3.402823466e38f;
            int bk = 0;
            #pragma unroll 1
            for (int c = 0; c < KCLS; ++c) {       // ascending, strict >
                float v = clsS[c];
                if (v > best) { best = v; bk = c; }
            }
            out[b * MTEST + m] = (float)bk;
        }
    }
}

// ---------------------------------------------------------------------------
extern "C" void kernel_launch(void* const* d_in, const int* in_sizes, int n_in,
                              void* d_out, int out_size) {
    const float* train;
    const float* test;
    if (in_sizes[0] == BATCH * TRN * DIM) {
        train = (const float*)d_in[0];
        test  = (const float*)d_in[1];
    } else {
        train = (const float*)d_in[1];
        test  = (const float*)d_in[0];
    }
    float* out = (float*)d_out;

    const int smem_bytes = SMEM_U32 * (int)sizeof(uint32_t);  // ~97 KB
    cudaFuncSetAttribute(ms_mma_kernel,
                         cudaFuncAttributeMaxDynamicSharedMemorySize, smem_bytes);

    dim3 grid(MTEST / TM, BATCH);
    ms_mma_kernel<<<grid, THREADS, smem_bytes>>>(train, test, out);

    zero_kernel<<<1, 1>>>();
    compact_kernel<<<(BATCH * MTEST) / 1024, 1024>>>();
    rescue_kernel<<<RGRID, 128>>>(train, test, out);
}

// round 16
// speedup vs baseline: 2.0340x; 1.3169x over previous
#include <cuda_runtime.h>
#include <cuda_bf16.h>
#include <cstdint>

#define BATCH   4
#define KCLS    64
#define NSHOT   32
#define DIM     128
#define MTEST   4096
#define TRN     (KCLS * NSHOT)      // 2048
#define TM      128                 // tests per CTA
#define TNC     64                  // trains per chunk (2 classes)
#define NCHUNK  (TRN / TNC)         // 32
#define THREADS 512                 // 16 warps: 8m x 2n grid of 16x32 warp tiles
#define EPS_RESCUE 1e-3f
#define RGRID   512                 // rescue worker grid

// smem u32 offsets: fragment-order tiles [t(8)][frag(8)][lane(32)][regs]
#define OFF_AHI  0                   // 8*8*32*4 = 8192 u32
#define OFF_ALO  8192
#define OFF_BHI  16384               // 8*8*32*2 = 4096 u32
#define OFF_BLO  20480
#define OFF_INVN 24576               // 64
#define OFF_TMP  24640               // 128
#define SMEM_U32 24768               // 99072 B

__device__ int g_flag[BATCH * MTEST];
__device__ int g_list[BATCH * MTEST];
__device__ int g_count;

// ---------------------------------------------------------------------------
// helpers
// ---------------------------------------------------------------------------
__device__ __forceinline__ uint32_t packbf(float x0, float x1) {
    __nv_bfloat162 h = __floats2bfloat162_rn(x0, x1);   // .x = x0 (low half)
    return *(uint32_t*)&h;
}
__device__ __forceinline__ float bfhi(float x) {
    return __bfloat162float(__float2bfloat16_rn(x));
}
__device__ __forceinline__ void mma_bf16(float* d, const uint32_t* a,
                                         const uint32_t* b) {
    asm volatile(
        "mma.sync.aligned.m16n8k16.row.col.f32.bf16.bf16.f32 "
        "{%0,%1,%2,%3}, {%4,%5,%6,%7}, {%8,%9}, {%0,%1,%2,%3};"
        : "+f"(d[0]), "+f"(d[1]), "+f"(d[2]), "+f"(d[3])
        : "r"(a[0]), "r"(a[1]), "r"(a[2]), "r"(a[3]), "r"(b[0]), "r"(b[1]));
}

extern __shared__ __align__(16) uint32_t sm[];

// ---------------------------------------------------------------------------
// Main kernel: 3x bf16-split mma.sync GEMM + fused max/argmax + rescue flag.
//   score(m,n) = dot(test, train_n) * invnorm(train_n)   (test norm dropped)
// 16 warps: warp w -> m-group mg = w>>1 (rows 16mg..16mg+15),
//           class parity nw = w&1. Warp tile 16m x 32n, 12 MMAs per k-slice.
// ---------------------------------------------------------------------------
__global__ __launch_bounds__(THREADS, 1)
void ms_mma_kernel(const float* __restrict__ train,
                   const float* __restrict__ test,
                   float* __restrict__ out) {
    const int tid  = threadIdx.x;
    const int lane = tid & 31;
    const int w    = tid >> 5;           // 0..15
    const int b      = blockIdx.y;
    const int m_base = blockIdx.x * TM;

    const float* teg = test  + ((size_t)b * MTEST + m_base) * DIM;
    const float* trg = train + (size_t)b * TRN * DIM;

    float* invnS = (float*)&sm[OFF_INVN];
    float* tmpS  = (float*)&sm[OFF_TMP];

    const int r4 = lane >> 2;            // 0..7
    const int c4 = lane & 3;             // 0..3

    // ---- A fragments (tests), built once: 64 tasks over 16 warps --------
    #pragma unroll
    for (int it = 0; it < 4; ++it) {
        int task = w + 16 * it;          // 0..63
        int mf = task & 7, t = task >> 3;
        int m = mf * 16 + r4;
        int k = t * 16 + 2 * c4;
        float2 x0 = *(const float2*)(teg + m * DIM + k);
        float2 x1 = *(const float2*)(teg + (m + 8) * DIM + k);
        float2 x2 = *(const float2*)(teg + m * DIM + k + 8);
        float2 x3 = *(const float2*)(teg + (m + 8) * DIM + k + 8);
        float h[8] = {bfhi(x0.x), bfhi(x0.y), bfhi(x1.x), bfhi(x1.y),
                      bfhi(x2.x), bfhi(x2.y), bfhi(x3.x), bfhi(x3.y)};
        uint4 ah = make_uint4(packbf(h[0], h[1]), packbf(h[2], h[3]),
                              packbf(h[4], h[5]), packbf(h[6], h[7]));
        uint4 al = make_uint4(packbf(x0.x - h[0], x0.y - h[1]),
                              packbf(x1.x - h[2], x1.y - h[3]),
                              packbf(x2.x - h[4], x2.y - h[5]),
                              packbf(x3.x - h[6], x3.y - h[7]));
        int base = ((t * 8 + mf) * 32 + lane) * 4;
        *(uint4*)&sm[OFF_AHI + base] = ah;
        *(uint4*)&sm[OFF_ALO + base] = al;
    }

    const int nw = w & 1;                // class parity within chunk
    const int mg = w >> 1;               // m-group (16 rows)

    float bestv[2], best2v[2];
    int   bestk[2];
    #pragma unroll
    for (int i = 0; i < 2; ++i) {
        bestv[i] = -3.402823466e38f; best2v[i] = -3.402823466e38f; bestk[i] = 0;
    }

    for (int chunk = 0; chunk < NCHUNK; ++chunk) {
        __syncthreads();   // prev compute done reading B frags / tmp / invn

        // ---- train-row inverse norms (warp per row, 4 rows/warp) ---------
        #pragma unroll
        for (int it = 0; it < 4; ++it) {
            int n = w + 16 * it;
            float4 v = *(const float4*)(trg + (size_t)(chunk * TNC + n) * DIM + lane * 4);
            float s = v.x * v.x + v.y * v.y + v.z * v.z + v.w * v.w;
            #pragma unroll
            for (int o = 16; o; o >>= 1) s += __shfl_xor_sync(0xffffffffu, s, o);
            if (lane == 0) invnS[n] = 1.0f / fmaxf(sqrtf(s), 1e-8f);
        }

        // ---- B fragments: 64 tasks over 16 warps -------------------------
        #pragma unroll
        for (int it = 0; it < 4; ++it) {
            int task = w + 16 * it;
            int nf = task & 7, t = task >> 3;
            int n = chunk * TNC + nf * 8 + r4;
            int k = t * 16 + 2 * c4;
            float2 y0 = *(const float2*)(trg + (size_t)n * DIM + k);
            float2 y1 = *(const float2*)(trg + (size_t)n * DIM + k + 8);
            float h0 = bfhi(y0.x), h1 = bfhi(y0.y);
            float h2 = bfhi(y1.x), h3 = bfhi(y1.y);
            int base = ((t * 8 + nf) * 32 + lane) * 2;
            *(uint2*)&sm[OFF_BHI + base] =
                make_uint2(packbf(h0, h1), packbf(h2, h3));
            *(uint2*)&sm[OFF_BLO + base] =
                make_uint2(packbf(y0.x - h0, y0.y - h1),
                           packbf(y1.x - h2, y1.y - h3));
        }
        __syncthreads();

        // ---- compute: warp tile 16m x 32n, 8 k16-slices x 3 split-MMAs ---
        float d[4][4];
        #pragma unroll
        for (int j = 0; j < 4; ++j)
            #pragma unroll
            for (int q = 0; q < 4; ++q) d[j][q] = 0.0f;

        #pragma unroll
        for (int t = 0; t < 8; ++t) {
            uint32_t ah[4], al[4];
            {
                int base = ((t * 8 + mg) * 32 + lane) * 4;
                *(uint4*)ah = *(const uint4*)&sm[OFF_AHI + base];
                *(uint4*)al = *(const uint4*)&sm[OFF_ALO + base];
            }
            uint32_t bh[4][2], bl[4][2];
            #pragma unroll
            for (int j = 0; j < 4; ++j) {
                int base = ((t * 8 + nw * 4 + j) * 32 + lane) * 2;
                *(uint2*)bh[j] = *(const uint2*)&sm[OFF_BHI + base];
                *(uint2*)bl[j] = *(const uint2*)&sm[OFF_BLO + base];
            }
            // split-major: 4 independent accumulators between same-d MMAs
            #pragma unroll
            for (int j = 0; j < 4; ++j) mma_bf16(d[j], ah, bh[j]);
            #pragma unroll
            for (int j = 0; j < 4; ++j) mma_bf16(d[j], ah, bl[j]);
            #pragma unroll
            for (int j = 0; j < 4; ++j) mma_bf16(d[j], al, bh[j]);
        }

        // ---- epilogue: invnorm fold, max over class shots -----------------
        float winv[4][2];
        #pragma unroll
        for (int j = 0; j < 4; ++j) {
            int ncol = nw * 32 + j * 8 + 2 * c4;
            winv[j][0] = invnS[ncol];
            winv[j][1] = invnS[ncol + 1];
        }

        float rowv[2];
        #pragma unroll
        for (int half = 0; half < 2; ++half) {
            float v = -3.402823466e38f;
            #pragma unroll
            for (int j = 0; j < 4; ++j)
                v = fmaxf(v, fmaxf(d[j][half * 2]     * winv[j][0],
                                   d[j][half * 2 + 1] * winv[j][1]));
            v = fmaxf(v, __shfl_xor_sync(0xffffffffu, v, 1));
            v = fmaxf(v, __shfl_xor_sync(0xffffffffu, v, 2));
            rowv[half] = v;              // valid on lanes with (lane&3)==0
        }

        // odd-class warps publish their class scores
        if (nw == 1 && c4 == 0) {
            #pragma unroll
            for (int half = 0; half < 2; ++half)
                tmpS[mg * 16 + half * 8 + r4] = rowv[half];
        }
        __syncthreads();
        // even-class warps do the running argmax (ascending class order)
        if (nw == 0 && c4 == 0) {
            #pragma unroll
            for (int half = 0; half < 2; ++half) {
                int row = mg * 16 + half * 8 + r4;
                float v0 = rowv[half];           // class 2*chunk
                float v1 = tmpS[row];            // class 2*chunk+1
                if (v0 > bestv[half]) { best2v[half] = bestv[half]; bestv[half] = v0; bestk[half] = 2 * chunk; }
                else if (v0 > best2v[half]) best2v[half] = v0;
                if (v1 > bestv[half]) { best2v[half] = bestv[half]; bestv[half] = v1; bestk[half] = 2 * chunk + 1; }
                else if (v1 > best2v[half]) best2v[half] = v1;
            }
        }
    }

    if (nw == 0 && c4 == 0) {
        #pragma unroll
        for (int half = 0; half < 2; ++half) {
            int row = mg * 16 + half * 8 + r4;
            int gm  = b * MTEST + m_base + row;
            out[gm]    = (float)bestk[half];
            g_flag[gm] = (bestv[half] - best2v[half] < EPS_RESCUE) ? 1 : 0;
        }
    }
}

// ---------------------------------------------------------------------------
// Rescue path: zero counter -> compact flagged indices -> fixed worker grid.
// Worker: 512 threads = one thread per train row per stripe; warp w covers
// exactly class w+16s (32 lanes = 32 shots -> one shfl-max per class).
// ---------------------------------------------------------------------------
__global__ void zero_kernel() { g_count = 0; }

__global__ __launch_bounds__(1024)
void compact_kernel() {
    int idx = blockIdx.x * 1024 + threadIdx.x;
    if (idx < BATCH * MTEST && g_flag[idx]) {
        int pos = atomicAdd(&g_count, 1);
        g_list[pos] = idx;
    }
}

__global__ __launch_bounds__(512, 1)
void rescue_kernel(const float* __restrict__ train,
                   const float* __restrict__ test,
                   float* __restrict__ out) {
    __shared__ __align__(16) float teS[DIM];
    __shared__ float clsS[KCLS];

    const int tid = threadIdx.x;
    const int w = tid >> 5, l = tid & 31;
    const int cnt = g_count;

    for (int q = blockIdx.x; q < cnt; q += RGRID) {
        int idx = g_list[q];
        int b = idx / MTEST, m = idx % MTEST;

        __syncthreads();
        if (tid < DIM) teS[tid] = test[((size_t)b * MTEST + m) * DIM + tid];
        __syncthreads();

        const float* trb = train + (size_t)b * TRN * DIM;
        #pragma unroll
        for (int s = 0; s < 4; ++s) {
            int n = s * 512 + tid;                 // class s*16+w, shot l
            const float4* tr4 = (const float4*)(trb + (size_t)n * DIM);
            float d0 = 0.0f, d1 = 0.0f, s0 = 0.0f, s1 = 0.0f;
            #pragma unroll
            for (int qq = 0; qq < 32; qq += 2) {
                float4 t0 = tr4[qq],     e0 = *(const float4*)(teS + qq * 4);
                float4 t1 = tr4[qq + 1], e1 = *(const float4*)(teS + qq * 4 + 4);
                d0 += t0.x * e0.x + t0.y * e0.y + t0.z * e0.z + t0.w * e0.w;
                s0 += t0.x * t0.x + t0.y * t0.y + t0.z * t0.z + t0.w * t0.w;
                d1 += t1.x * e1.x + t1.y * e1.y + t1.z * e1.z + t1.w * e1.w;
                s1 += t1.x * t1.x + t1.y * t1.y + t1.z * t1.z + t1.w * t1.w;
            }
            float sc = (d0 + d1) * (1.0f / fmaxf(sqrtf(s0 + s1), 1e-8f));
            #pragma unroll
            for (int o = 16; o; o >>= 1)
                sc = fmaxf(sc, __shfl_xor_sync(0xffffffffu, sc, o));
            if (l == 0) clsS[s * 16 + w] = sc;
        }
        __syncthreads();

        if (tid == 0) {
            float best = -3.402823466e38f;
            int bk = 0;
            #pragma unroll 1
            for (int c = 0; c < KCLS; ++c) {       // ascending, strict >
                float v = clsS[c];
                if (v > best) { best = v; bk = c; }
            }
            out[b * MTEST + m] = (float)bk;
        }
    }
}

// ---------------------------------------------------------------------------
extern "C" void kernel_launch(void* const* d_in, const int* in_sizes, int n_in,
                              void* d_out, int out_size) {
    const float* train;
    const float* test;
    if (in_sizes[0] == BATCH * TRN * DIM) {
        train = (const float*)d_in[0];
        test  = (const float*)d_in[1];
    } else {
        train = (const float*)d_in[1];
        test  = (const float*)d_in[0];
    }
    float* out = (float*)d_out;

    const int smem_bytes = SMEM_U32 * (int)sizeof(uint32_t);  // ~97 KB
    cudaFuncSetAttribute(ms_mma_kernel,
                         cudaFuncAttributeMaxDynamicSharedMemorySize, smem_bytes);

    dim3 grid(MTEST / TM, BATCH);
    ms_mma_kernel<<<grid, THREADS, smem_bytes>>>(train, test, out);

    zero_kernel<<<1, 1>>>();
    compact_kernel<<<(BATCH * MTEST) / 1024, 1024>>>();
    rescue_kernel<<<RGRID, 512>>>(train, test, out);
}

// round 17
// speedup vs baseline: 2.3656x; 1.1630x over previous
#include <cuda_runtime.h>
#include <cuda_bf16.h>
#include <cstdint>

#define BATCH   4
#define KCLS    64
#define NSHOT   32
#define DIM     128
#define MTEST   4096
#define TRN     (KCLS * NSHOT)      // 2048
#define TM      128                 // tests per CTA
#define TNC     128                 // trains per chunk (4 classes)
#define NCHUNK  (TRN / TNC)         // 16
#define THREADS 512                 // 16 warps: 8m x 2n, warp tile 16m x 64n
#define EPS_RESCUE 4e-4f
#define RGRID   512                 // rescue worker grid

// smem u32 offsets: fragment-order tiles
//   A: [t(8)][mf(8)][lane(32)][4]   B: [t(8)][nf(16)][lane(32)][2]
#define OFF_AHI  0                   // 8192 u32
#define OFF_ALO  8192                // 8192
#define OFF_BHI  16384               // 8*16*32*2 = 8192
#define OFF_BLO  24576               // 8192
#define OFF_INVN 32768               // 128
#define OFF_TMP  32896               // 256 (2 classes x 128 rows)
#define SMEM_U32 33152               // 132608 B

__device__ int g_flag[BATCH * MTEST];
__device__ int g_list[BATCH * MTEST];
__device__ unsigned long long g_best[BATCH * MTEST];
__device__ int g_count;

typedef unsigned long long ull;

// ---------------------------------------------------------------------------
// helpers
// ---------------------------------------------------------------------------
__device__ __forceinline__ uint32_t packbf(float x0, float x1) {
    __nv_bfloat162 h = __floats2bfloat162_rn(x0, x1);   // .x = x0 (low half)
    return *(uint32_t*)&h;
}
__device__ __forceinline__ float bfhi(float x) {
    return __bfloat162float(__float2bfloat16_rn(x));
}
__device__ __forceinline__ void mma_bf16(float* d, const uint32_t* a,
                                         const uint32_t* b) {
    asm volatile(
        "mma.sync.aligned.m16n8k16.row.col.f32.bf16.bf16.f32 "
        "{%0,%1,%2,%3}, {%4,%5,%6,%7}, {%8,%9}, {%0,%1,%2,%3};"
        : "+f"(d[0]), "+f"(d[1]), "+f"(d[2]), "+f"(d[3])
        : "r"(a[0]), "r"(a[1]), "r"(a[2]), "r"(a[3]), "r"(b[0]), "r"(b[1]));
}
// order-preserving float encode; ties broken toward SMALLER class (first-max)
__device__ __forceinline__ ull enc_score(float f, int cls) {
    uint32_t bits = __float_as_uint(f);
    uint32_t e = (bits & 0x80000000u) ? ~bits : (bits | 0x80000000u);
    return ((ull)e << 32) | (uint32_t)(KCLS - 1 - cls);
}

extern __shared__ __align__(16) uint32_t sm[];

// ---------------------------------------------------------------------------
// Main kernel: 3x bf16-split mma.sync GEMM + fused max/argmax + rescue flag.
//   score(m,n) = dot(test, train_n) * invnorm(train_n)   (test norm dropped)
// 16 warps: warp w -> m-group mg=w>>1 (16 rows), n-half nw=w&1 (64 trains
// = 2 classes). Warp tile 16m x 64n: 8 independent accumulators, 24 MMAs
// per k16-slice in split-major order.
// ---------------------------------------------------------------------------
__global__ __launch_bounds__(THREADS, 1)
void ms_mma_kernel(const float* __restrict__ train,
                   const float* __restrict__ test,
                   float* __restrict__ out) {
    const int tid  = threadIdx.x;
    const int lane = tid & 31;
    const int w    = tid >> 5;           // 0..15
    const int b      = blockIdx.y;
    const int m_base = blockIdx.x * TM;

    const float* teg = test  + ((size_t)b * MTEST + m_base) * DIM;
    const float* trg = train + (size_t)b * TRN * DIM;

    float* invnS = (float*)&sm[OFF_INVN];
    float* tmpS  = (float*)&sm[OFF_TMP];

    const int r4 = lane >> 2;            // 0..7
    const int c4 = lane & 3;             // 0..3

    // ---- A fragments (tests), built once: 64 tasks over 16 warps --------
    #pragma unroll
    for (int it = 0; it < 4; ++it) {
        int task = w + 16 * it;          // 0..63
        int mf = task & 7, t = task >> 3;
        int m = mf * 16 + r4;
        int k = t * 16 + 2 * c4;
        float2 x0 = *(const float2*)(teg + m * DIM + k);
        float2 x1 = *(const float2*)(teg + (m + 8) * DIM + k);
        float2 x2 = *(const float2*)(teg + m * DIM + k + 8);
        float2 x3 = *(const float2*)(teg + (m + 8) * DIM + k + 8);
        float h[8] = {bfhi(x0.x), bfhi(x0.y), bfhi(x1.x), bfhi(x1.y),
                      bfhi(x2.x), bfhi(x2.y), bfhi(x3.x), bfhi(x3.y)};
        uint4 ah = make_uint4(packbf(h[0], h[1]), packbf(h[2], h[3]),
                              packbf(h[4], h[5]), packbf(h[6], h[7]));
        uint4 al = make_uint4(packbf(x0.x - h[0], x0.y - h[1]),
                              packbf(x1.x - h[2], x1.y - h[3]),
                              packbf(x2.x - h[4], x2.y - h[5]),
                              packbf(x3.x - h[6], x3.y - h[7]));
        int base = ((t * 8 + mf) * 32 + lane) * 4;
        *(uint4*)&sm[OFF_AHI + base] = ah;
        *(uint4*)&sm[OFF_ALO + base] = al;
    }

    const int nw = w & 1;                // n-half: 64 trains = 2 classes
    const int mg = w >> 1;               // m-group (16 rows)

    float bestv[2], best2v[2];
    int   bestk[2];
    #pragma unroll
    for (int i = 0; i < 2; ++i) {
        bestv[i] = -3.402823466e38f; best2v[i] = -3.402823466e38f; bestk[i] = 0;
    }

    for (int chunk = 0; chunk < NCHUNK; ++chunk) {
        const int rowBase = chunk * TNC;

        __syncthreads();   // prev compute done reading B frags / tmp / invn

        // ---- train-row inverse norms (128 rows over 16 warps) ------------
        #pragma unroll
        for (int it = 0; it < 8; ++it) {
            int n = w + 16 * it;
            float4 v = *(const float4*)(trg + (size_t)(rowBase + n) * DIM + lane * 4);
            float s = v.x * v.x + v.y * v.y + v.z * v.z + v.w * v.w;
            #pragma unroll
            for (int o = 16; o; o >>= 1) s += __shfl_xor_sync(0xffffffffu, s, o);
            if (lane == 0) invnS[n] = 1.0f / fmaxf(sqrtf(s), 1e-8f);
        }

        // ---- B fragments: 128 tasks (16 nf x 8 t) over 16 warps ----------
        #pragma unroll
        for (int it = 0; it < 8; ++it) {
            int task = w + 16 * it;
            int nf = task & 15, t = task >> 4;
            int n = rowBase + nf * 8 + r4;
            int k = t * 16 + 2 * c4;
            float2 y0 = *(const float2*)(trg + (size_t)n * DIM + k);
            float2 y1 = *(const float2*)(trg + (size_t)n * DIM + k + 8);
            float h0 = bfhi(y0.x), h1 = bfhi(y0.y);
            float h2 = bfhi(y1.x), h3 = bfhi(y1.y);
            int base = ((t * 16 + nf) * 32 + lane) * 2;
            *(uint2*)&sm[OFF_BHI + base] =
                make_uint2(packbf(h0, h1), packbf(h2, h3));
            *(uint2*)&sm[OFF_BLO + base] =
                make_uint2(packbf(y0.x - h0, y0.y - h1),
                           packbf(y1.x - h2, y1.y - h3));
        }
        __syncthreads();

        // ---- compute: warp tile 16m x 64n, 8 k16-slices x 24 MMAs --------
        float d[8][4];
        #pragma unroll
        for (int j = 0; j < 8; ++j)
            #pragma unroll
            for (int q = 0; q < 4; ++q) d[j][q] = 0.0f;

        #pragma unroll
        for (int t = 0; t < 8; ++t) {
            uint32_t ah[4], al[4];
            {
                int base = ((t * 8 + mg) * 32 + lane) * 4;
                *(uint4*)ah = *(const uint4*)&sm[OFF_AHI + base];
                *(uint4*)al = *(const uint4*)&sm[OFF_ALO + base];
            }
            uint32_t bh[8][2], bl[8][2];
            #pragma unroll
            for (int j = 0; j < 8; ++j) {
                int base = ((t * 16 + nw * 8 + j) * 32 + lane) * 2;
                *(uint2*)bh[j] = *(const uint2*)&sm[OFF_BHI + base];
                *(uint2*)bl[j] = *(const uint2*)&sm[OFF_BLO + base];
            }
            // split-major: 8 independent accumulators between same-d MMAs
            #pragma unroll
            for (int j = 0; j < 8; ++j) mma_bf16(d[j], ah, bh[j]);
            #pragma unroll
            for (int j = 0; j < 8; ++j) mma_bf16(d[j], ah, bl[j]);
            #pragma unroll
            for (int j = 0; j < 8; ++j) mma_bf16(d[j], al, bh[j]);
        }

        // ---- epilogue: invnorm fold, class max over 32 shots --------------
        float winv[8][2];
        #pragma unroll
        for (int j = 0; j < 8; ++j) {
            int ncol = nw * 64 + j * 8 + 2 * c4;
            winv[j][0] = invnS[ncol];
            winv[j][1] = invnS[ncol + 1];
        }

        float rowv[2][2];   // [half][class-within-warp]
        #pragma unroll
        for (int half = 0; half < 2; ++half)
            #pragma unroll
            for (int cj = 0; cj < 2; ++cj) {
                float v = -3.402823466e38f;
                #pragma unroll
                for (int jj = 0; jj < 4; ++jj) {
                    int j = cj * 4 + jj;
                    v = fmaxf(v, fmaxf(d[j][half * 2]     * winv[j][0],
                                       d[j][half * 2 + 1] * winv[j][1]));
                }
                v = fmaxf(v, __shfl_xor_sync(0xffffffffu, v, 1));
                v = fmaxf(v, __shfl_xor_sync(0xffffffffu, v, 2));
                rowv[half][cj] = v;      // valid on lanes with (lane&3)==0
            }

        // odd n-half warps (classes 4c+2, 4c+3) publish
        if (nw == 1 && c4 == 0) {
            #pragma unroll
            for (int half = 0; half < 2; ++half)
                #pragma unroll
                for (int cj = 0; cj < 2; ++cj)
                    tmpS[cj * 128 + mg * 16 + half * 8 + r4] = rowv[half][cj];
        }
        __syncthreads();
        // even n-half warps: running argmax, ascending class order, strict >
        if (nw == 0 && c4 == 0) {
            #pragma unroll
            for (int half = 0; half < 2; ++half) {
                int row = mg * 16 + half * 8 + r4;
                float vc[4];
                vc[0] = rowv[half][0];           // class 4*chunk
                vc[1] = rowv[half][1];           // class 4*chunk+1
                vc[2] = tmpS[row];               // class 4*chunk+2
                vc[3] = tmpS[128 + row];         // class 4*chunk+3
                #pragma unroll
                for (int cc = 0; cc < 4; ++cc) {
                    float v = vc[cc];
                    if (v > bestv[half]) {
                        best2v[half] = bestv[half];
                        bestv[half] = v; bestk[half] = 4 * chunk + cc;
                    } else if (v > best2v[half]) best2v[half] = v;
                }
            }
        }
    }

    if (nw == 0 && c4 == 0) {
        #pragma unroll
        for (int half = 0; half < 2; ++half) {
            int row = mg * 16 + half * 8 + r4;
            int gm  = b * MTEST + m_base + row;
            out[gm]    = (float)bestk[half];
            g_flag[gm] = (bestv[half] - best2v[half] < EPS_RESCUE) ? 1 : 0;
        }
    }
}

// ---------------------------------------------------------------------------
// Rescue path: zero -> compact -> stripe-parallel worker (atomicMax combine)
// -> finalize. Worker task = (item q, stripe s): 512 threads = one per train
// row; warp w covers exactly class 16s+w (32 lanes = 32 shots).
// ---------------------------------------------------------------------------
__global__ void zero_kernel() { g_count = 0; }

__global__ __launch_bounds__(1024)
void compact_kernel() {
    int idx = blockIdx.x * 1024 + threadIdx.x;
    if (idx < BATCH * MTEST && g_flag[idx]) {
        int pos = atomicAdd(&g_count, 1);
        g_list[pos] = idx;
        g_best[pos] = 0ULL;              // below any encoded finite score
    }
}

__global__ __launch_bounds__(512, 1)
void rescue_kernel(const float* __restrict__ train,
                   const float* __restrict__ test) {
    __shared__ __align__(16) float teS[DIM];

    const int tid = threadIdx.x;
    const int w = tid >> 5, l = tid & 31;
    const int ntask = g_count * 4;

    for (int task = blockIdx.x; task < ntask; task += RGRID) {
        int q = task >> 2, s = task & 3;
        int idx = g_list[q];
        int b = idx / MTEST, m = idx % MTEST;

        __syncthreads();
        if (tid < DIM) teS[tid] = test[((size_t)b * MTEST + m) * DIM + tid];
        __syncthreads();

        const float* trb = train + (size_t)b * TRN * DIM;
        int n = s * 512 + tid;                 // class s*16+w, shot l
        const float4* tr4 = (const float4*)(trb + (size_t)n * DIM);
        float d0 = 0.0f, d1 = 0.0f, s0 = 0.0f, s1 = 0.0f;
        #pragma unroll
        for (int qq = 0; qq < 32; qq += 2) {
            float4 t0 = tr4[qq],     e0 = *(const float4*)(teS + qq * 4);
            float4 t1 = tr4[qq + 1], e1 = *(const float4*)(teS + qq * 4 + 4);
            d0 += t0.x * e0.x + t0.y * e0.y + t0.z * e0.z + t0.w * e0.w;
            s0 += t0.x * t0.x + t0.y * t0.y + t0.z * t0.z + t0.w * t0.w;
            d1 += t1.x * e1.x + t1.y * e1.y + t1.z * e1.z + t1.w * e1.w;
            s1 += t1.x * t1.x + t1.y * t1.y + t1.z * t1.z + t1.w * t1.w;
        }
        float sc = (d0 + d1) * (1.0f / fmaxf(sqrtf(s0 + s1), 1e-8f));
        #pragma unroll
        for (int o = 16; o; o >>= 1)
            sc = fmaxf(sc, __shfl_xor_sync(0xffffffffu, sc, o));
        if (l == 0) atomicMax(&g_best[q], enc_score(sc, s * 16 + w));
    }
}

__global__ __launch_bounds__(1024)
void finalize_kernel(float* __restrict__ out) {
    int i = blockIdx.x * 1024 + threadIdx.x;
    if (i < g_count) {
        int cls = KCLS - 1 - (int)(g_best[i] & 0xFFFFFFFFu);
        out[g_list[i]] = (float)cls;
    }
}

// ---------------------------------------------------------------------------
extern "C" void kernel_launch(void* const* d_in, const int* in_sizes, int n_in,
                              void* d_out, int out_size) {
    const float* train;
    const float* test;
    if (in_sizes[0] == BATCH * TRN * DIM) {
        train = (const float*)d_in[0];
        test  = (const float*)d_in[1];
    } else {
        train = (const float*)d_in[1];
        test  = (const float*)d_in[0];
    }
    float* out = (float*)d_out;

    const int smem_bytes = SMEM_U32 * (int)sizeof(uint32_t);  // ~130 KB
    cudaFuncSetAttribute(ms_mma_kernel,
                         cudaFuncAttributeMaxDynamicSharedMemorySize, smem_bytes);

    dim3 grid(MTEST / TM, BATCH);
    ms_mma_kernel<<<grid, THREADS, smem_bytes>>>(train, test, out);

    zero_kernel<<<1, 1>>>();
    compact_kernel<<<(BATCH * MTEST) / 1024, 1024>>>();
    rescue_kernel<<<RGRID, 512>>>(train, test);
    finalize_kernel<<<(BATCH * MTEST) / 1024, 1024>>>(out);
}